// round 10
// baseline (speedup 1.0000x reference)
#include <cuda_runtime.h>
#include <cstdint>

#define Bn 16
#define Nn 1024

// Scratch (device globals; no allocation allowed). 128B-aligned so each
// (m, e) sagg segment of 128B sits in exactly one cache line.
__device__ __align__(128) float g_S[Bn * Nn * 96];     // x@W0 + b0      [row][ec]
__device__ __align__(128) float g_sagg[Bn * Nn * 96];  // dis[m,e]*(x@W) [row][ec]
__device__ __align__(128) float g_dis[Bn * Nn * 3];    // deg^-1/2       [row][e]

#define FFMA2(d, a, b) \
    asm volatile("fma.rn.f32x2 %0, %1, %2, %0;" : "+l"(d) : "l"(a), "l"(b))
#define DUP2(d, a) \
    asm volatile("mov.b64 %0, {%1,%1};" : "=l"(d) : "f"(a))
#define UNPACK2(lo, hi, v) \
    asm volatile("mov.b64 {%0,%1}, %2;" : "=f"(lo), "=f"(hi) : "l"(v))
#define GETC(v, j) ((j) == 0 ? (v).x : (j) == 1 ? (v).y : (j) == 2 ? (v).z : (v).w)

// ---------------------------------------------------------------------------
// Kernel 1 (fused): degrees + per-row linears.  One block (128 thr) per row.
//   deg[e] = sum_m adj[row][m][e];  dis = rsqrt(max(deg,1))  -> g_dis
//   g_sagg[row][ec] = dis[e] * (x[row]@W)[ec];  g_S = x@W0 + b0
// 6 independent float4 loads per thread (MLP 6); W/W0 L1-resident.
// ---------------------------------------------------------------------------
__global__ __launch_bounds__(128) void deg_kernel(
    const float* __restrict__ adj, const float* __restrict__ x,
    const float* __restrict__ W, const float* __restrict__ W0,
    const float* __restrict__ b0)
{
    int row = blockIdx.x;                    // b*N + n
    const float4* base = (const float4*)(adj + (size_t)row * 3072);
    int t = threadIdx.x;

    __shared__ float xsh[32];
    if (t < 32) xsh[t] = x[(size_t)row * 32 + t];

    float s0 = 0.f, s1 = 0.f, s2 = 0.f;
#pragma unroll 6
    for (int it = 0; it < 6; it++) {
        int q = t + it * 128;                // float4 index, 768 total
        float4 v = base[q];
        int e0 = q % 3;                      // (4q)%3 == q%3
        if (e0 == 0)      { s0 += v.x; s1 += v.y; s2 += v.z; s0 += v.w; }
        else if (e0 == 1) { s1 += v.x; s2 += v.y; s0 += v.z; s1 += v.w; }
        else              { s2 += v.x; s0 += v.y; s1 += v.z; s2 += v.w; }
    }
#pragma unroll
    for (int off = 16; off; off >>= 1) {
        s0 += __shfl_down_sync(0xffffffffu, s0, off);
        s1 += __shfl_down_sync(0xffffffffu, s1, off);
        s2 += __shfl_down_sync(0xffffffffu, s2, off);
    }
    __shared__ float red[4][3];
    __shared__ float dis_s[3];
    int w = t >> 5, lane = t & 31;
    if (lane == 0) { red[w][0] = s0; red[w][1] = s1; red[w][2] = s2; }
    __syncthreads();
    if (t < 3) {
        float tot = red[0][t] + red[1][t] + red[2][t] + red[3][t];
        float d = rsqrtf(fmaxf(tot, 1.0f));
        dis_s[t] = d;
        g_dis[(size_t)row * 3 + t] = d;
    }
    __syncthreads();

    if (t < 96) {                            // both linears per thread
        float a = 0.f, a0 = 0.f;
#pragma unroll
        for (int k = 0; k < 32; k++) {
            float xv = xsh[k];
            a  += xv * __ldg(W  + k * 96 + t);
            a0 += xv * __ldg(W0 + k * 96 + t);
        }
        g_sagg[(size_t)row * 96 + t] = dis_s[t >> 5] * a;
        g_S[(size_t)row * 96 + t]    = a0 + __ldg(b0 + t);
    }
}

// ---------------------------------------------------------------------------
// Kernel 2: aggregation GEMM — no shared memory, all operands via LDG.
//   out[b,n,c] = mask * ( sum_e dis[n,e] * sum_m adj[b,n,m,e]*sagg[b,m,ec]
//                         + sum_e S[b,n,ec] )
// Block = 64 thr (2 warps); warp covers 32 rows? no: warp covers 16 rows.
// Lane = (rp = lane>>4, cq = lane&15): lane accumulates rows
// rowbase..rowbase+7 (its rp-octet) for the c-pair (2cq, 2cq+1), all 3 e.
// m in subchunks of 8:
//   - sagg: 24 LDG.64 (16 lanes x 8B = one 128B line; L1-hot), kept in regs
//     and reused across all 16 rows of the warp.
//   - adj: per row 6 LDG.128 (2 distinct lines/warp-instr: one per rp-octet),
//     scalars dup'd to f32x2 with one mov.b64 (alu pipe).
// No barriers, no cross-lane reduction; epilogue writes STG.64 c-pairs.
// ---------------------------------------------------------------------------
__global__ __launch_bounds__(64) void agg_kernel(
    const float* __restrict__ adj,
    const int* __restrict__ mask,
    float* __restrict__ out)
{
    int t = threadIdx.x, w = t >> 5, lane = t & 31;
    int rp = lane >> 4, cq = lane & 15;
    int b = blockIdx.y;
    int rowbase = blockIdx.x * 32 + w * 16 + rp * 8;   // lane's row octet

    const float* adjr = adj + ((size_t)b * Nn + rowbase) * 3072;
    const float* sgb  = g_sagg + (size_t)b * Nn * 96 + cq * 2;

    unsigned long long acc2[8][3];
#pragma unroll
    for (int i = 0; i < 8; i++)
#pragma unroll
        for (int e = 0; e < 3; e++) acc2[i][e] = 0ull;

    for (int m0 = 0; m0 < Nn; m0 += 8) {
        // sagg subchunk -> registers (shared across all 16 rows of the warp)
        unsigned long long sg[8][3];
#pragma unroll
        for (int j = 0; j < 8; j++)
#pragma unroll
            for (int e = 0; e < 3; e++)
                sg[j][e] = *(const unsigned long long*)(sgb + (size_t)(m0 + j) * 96 + e * 32);

        const float* ap = adjr + m0 * 3;
#pragma unroll
        for (int i = 0; i < 8; i++) {                   // row within octet
            float4 av[6];                               // 24 adj floats
#pragma unroll
            for (int s = 0; s < 6; s++)
                av[s] = *(const float4*)(ap + (size_t)i * 3072 + s * 4);
#pragma unroll
            for (int j = 0; j < 8; j++) {
#pragma unroll
                for (int e = 0; e < 3; e++) {
                    const int kl = j * 3 + e;
                    const int s = kl >> 2, cmp = kl & 3;
                    unsigned long long a2;
                    float a = GETC(av[s], cmp);
                    DUP2(a2, a);
                    FFMA2(acc2[i][e], a2, sg[j][e]);
                }
            }
        }
    }

    // epilogue
#pragma unroll
    for (int i = 0; i < 8; i++) {
        size_t rown = (size_t)b * Nn + rowbase + i;
        float d0 = g_dis[rown * 3 + 0];
        float d1 = g_dis[rown * 3 + 1];
        float d2 = g_dis[rown * 3 + 2];
        const float* Sp = g_S + rown * 96 + cq * 2;
        float2 S0 = *(const float2*)(Sp);
        float2 S1 = *(const float2*)(Sp + 32);
        float2 S2 = *(const float2*)(Sp + 64);
        float lo, hi;
        float2 o;
        UNPACK2(lo, hi, acc2[i][0]);
        o.x = d0 * lo; o.y = d0 * hi;
        UNPACK2(lo, hi, acc2[i][1]);
        o.x += d1 * lo; o.y += d1 * hi;
        UNPACK2(lo, hi, acc2[i][2]);
        o.x += d2 * lo; o.y += d2 * hi;
        o.x += S0.x + S1.x + S2.x;
        o.y += S0.y + S1.y + S2.y;
        if (mask[rown] == 0) { o.x = 0.f; o.y = 0.f; }
        *(float2*)(out + rown * 32 + cq * 2) = o;
    }
}

// ---------------------------------------------------------------------------
extern "C" void kernel_launch(void* const* d_in, const int* in_sizes, int n_in,
                              void* d_out, int out_size)
{
    const float* x    = (const float*)d_in[0];   // [16,1024,32]
    const float* adj  = (const float*)d_in[1];   // [16,1024,1024,3]
    const int*   mask = (const int*)d_in[2];     // [16,1024] bool -> int32
    const float* W    = (const float*)d_in[3];   // [32,96]
    const float* W0   = (const float*)d_in[4];   // [32,96]
    const float* b0   = (const float*)d_in[5];   // [96]
    float*       out  = (float*)d_out;           // [16,1024,32]

    (void)in_sizes; (void)n_in; (void)out_size;

    deg_kernel<<<Bn * Nn, 128>>>(adj, x, W, W0, b0);
    agg_kernel<<<dim3(Nn / 32, Bn), 64>>>(adj, mask, out);
}

// round 11
// speedup vs baseline: 2.2665x; 2.2665x over previous
#include <cuda_runtime.h>
#include <cstdint>

#define Bn 16
#define Nn 1024

// Scratch (device globals; no allocation allowed). 128B alignment makes every
// (m, e) sagg segment (32 floats) exactly one cache line.
__device__ __align__(128) float g_S[Bn * Nn * 96];     // x@W0 + b0      [row][ec]
__device__ __align__(128) float g_sagg[Bn * Nn * 96];  // dis[m,e]*(x@W) [row][ec]
__device__ __align__(128) float g_dis[Bn * Nn * 3];    // deg^-1/2       [row][e]

#define FFMA2(d, a, b) \
    asm volatile("fma.rn.f32x2 %0, %1, %2, %0;" : "+l"(d) : "l"(a), "l"(b))
#define DUP2(d, a) \
    asm volatile("mov.b64 %0, {%1,%1};" : "=l"(d) : "f"(a))
#define UNPACK2(lo, hi, v) \
    asm volatile("mov.b64 {%0,%1}, %2;" : "=f"(lo), "=f"(hi) : "l"(v))
#define GETC(v, j) ((j) == 0 ? (v).x : (j) == 1 ? (v).y : (j) == 2 ? (v).z : (v).w)

// ---------------------------------------------------------------------------
// Kernel 1 (fused): degrees + per-row linears.  One block (128 thr) per row.
// Each thread reads 3 CONSECUTIVE float4 (48B) so the e-phase of every
// component is compile-time (q0 = 3*(t + 128*it) === 0 mod 3) -> no divergence.
//   dis = rsqrt(max(deg,1)) -> g_dis
//   g_sagg[row][ec] = dis[e] * (x[row]@W)[ec];  g_S = x@W0 + b0
// ---------------------------------------------------------------------------
__global__ __launch_bounds__(128) void deg_kernel(
    const float* __restrict__ adj, const float* __restrict__ x,
    const float* __restrict__ W, const float* __restrict__ W0,
    const float* __restrict__ b0)
{
    int row = blockIdx.x;                    // b*N + n
    const float4* base = (const float4*)(adj + (size_t)row * 3072);
    int t = threadIdx.x;

    __shared__ float xsh[32];
    if (t < 32) xsh[t] = x[(size_t)row * 32 + t];

    float s0 = 0.f, s1 = 0.f, s2 = 0.f;
#pragma unroll
    for (int it = 0; it < 2; it++) {
        int q0 = 3 * (t + it * 128);         // q0 % 3 == 0 always
        float4 v0 = base[q0];
        float4 v1 = base[q0 + 1];
        float4 v2 = base[q0 + 2];
        // v0 e-pattern: 0,1,2,0 ; v1: 1,2,0,1 ; v2: 2,0,1,2
        s0 += v0.x + v0.w + v1.z + v2.y;
        s1 += v0.y + v1.x + v1.w + v2.z;
        s2 += v0.z + v1.y + v2.x + v2.w;
    }
#pragma unroll
    for (int off = 16; off; off >>= 1) {
        s0 += __shfl_down_sync(0xffffffffu, s0, off);
        s1 += __shfl_down_sync(0xffffffffu, s1, off);
        s2 += __shfl_down_sync(0xffffffffu, s2, off);
    }
    __shared__ float red[4][3];
    __shared__ float dis_s[3];
    int w = t >> 5, lane = t & 31;
    if (lane == 0) { red[w][0] = s0; red[w][1] = s1; red[w][2] = s2; }
    __syncthreads();
    if (t < 3) {
        float tot = red[0][t] + red[1][t] + red[2][t] + red[3][t];
        float d = rsqrtf(fmaxf(tot, 1.0f));
        dis_s[t] = d;
        g_dis[(size_t)row * 3 + t] = d;
    }
    __syncthreads();

    if (t < 96) {                            // both linears per thread
        float a = 0.f, a0 = 0.f;
#pragma unroll
        for (int k = 0; k < 32; k++) {
            float xv = xsh[k];
            a  += xv * __ldg(W  + k * 96 + t);
            a0 += xv * __ldg(W0 + k * 96 + t);
        }
        g_sagg[(size_t)row * 96 + t] = dis_s[t >> 5] * a;
        g_S[(size_t)row * 96 + t]    = a0 + __ldg(b0 + t);
    }
}

// ---------------------------------------------------------------------------
// Kernel 2: aggregation GEMM, k-split lanes, no shared memory.
//   out[b,n,c] = mask * ( sum_e dis[n,e] * sum_m adj[b,n,m,e]*sagg[b,m,ec]
//                         + sum_e S[b,n,ec] )
// Block = 256 thr (8 warps, 64 rows); warp owns 8 rows SHARED by all lanes.
// Lane = (kp = lane>>4, cq = lane&15): kp halves split the m-stream (kp=0
// handles m0..m0+3 of each 8-m superchunk, kp=1 handles m0+4..m0+7); cq owns
// the c-pair (2cq, 2cq+1).  Accumulators acc2[8 rows][3 e] (f32x2 over c).
//   - A (adj): 3 LDG.128 per row per 4-own-m (12 contiguous floats); only 2
//     distinct addresses per warp instr (kp), 48B apart -> ~1.4 lines.
//   - B (sagg): LDG.64; 16 cq lanes cover one full 128B (m,e) line per kp
//     half -> 2 lines/instr, zero redundancy; L1-resident across warps.
// kp-partials merged at the end with shfl_xor(16); kp splits the stores.
// ---------------------------------------------------------------------------
__global__ __launch_bounds__(256, 2) void agg_kernel(
    const float* __restrict__ adj,
    const int* __restrict__ mask,
    float* __restrict__ out)
{
    int t = threadIdx.x, w = t >> 5, lane = t & 31;
    int kp = lane >> 4, cq = lane & 15;
    int b = blockIdx.y;
    int rowbase = blockIdx.x * 64 + w * 8;            // warp's 8 rows

    const float* adjr = adj + ((size_t)b * Nn + rowbase) * 3072;
    const float* sgb  = g_sagg + (size_t)b * Nn * 96 + cq * 2;

    unsigned long long acc2[8][3];
#pragma unroll
    for (int i = 0; i < 8; i++)
#pragma unroll
        for (int e = 0; e < 3; e++) acc2[i][e] = 0ull;

    for (int m0 = 0; m0 < Nn; m0 += 8) {
        int myM = m0 + kp * 4;                        // this half's 4 m's

        // B: 12 c-pairs (4 m x 3 e), register-resident, reused by 8 rows
        unsigned long long bv[4][3];
#pragma unroll
        for (int j = 0; j < 4; j++)
#pragma unroll
            for (int e = 0; e < 3; e++)
                bv[j][e] = __ldg((const unsigned long long*)
                                 (sgb + (size_t)(myM + j) * 96 + e * 32));

        const float* ap = adjr + (size_t)myM * 3;
#pragma unroll
        for (int i = 0; i < 8; i++) {                 // rows (warp-shared)
            float4 a0 = *(const float4*)(ap + (size_t)i * 3072);
            float4 a1 = *(const float4*)(ap + (size_t)i * 3072 + 4);
            float4 a2 = *(const float4*)(ap + (size_t)i * 3072 + 8);
#pragma unroll
            for (int j = 0; j < 4; j++) {
#pragma unroll
                for (int e = 0; e < 3; e++) {
                    const int idx = j * 3 + e;        // 0..11, e = idx%3
                    const int s = idx >> 2, cmp = idx & 3;
                    float a = (s == 0) ? GETC(a0, cmp)
                            : (s == 1) ? GETC(a1, cmp) : GETC(a2, cmp);
                    unsigned long long a2r;
                    DUP2(a2r, a);
                    FFMA2(acc2[i][e], a2r, bv[j][e]);
                }
            }
        }
    }

    // merge kp halves (lanes xor 16 hold complementary m-partials)
#pragma unroll
    for (int i = 0; i < 8; i++)
#pragma unroll
        for (int e = 0; e < 3; e++) {
            float lo, hi;
            UNPACK2(lo, hi, acc2[i][e]);
            lo += __shfl_xor_sync(0xffffffffu, lo, 16);
            hi += __shfl_xor_sync(0xffffffffu, hi, 16);
            asm volatile("mov.b64 %0, {%1,%2};" : "=l"(acc2[i][e]) : "f"(lo), "f"(hi));
        }

    // epilogue: kp=0 stores rows 0..3, kp=1 stores rows 4..7
#pragma unroll
    for (int q = 0; q < 4; q++) {
        int i = kp * 4 + q;
        size_t rown = (size_t)b * Nn + rowbase + i;
        float d0 = g_dis[rown * 3 + 0];
        float d1 = g_dis[rown * 3 + 1];
        float d2 = g_dis[rown * 3 + 2];
        const float* Sp = g_S + rown * 96 + cq * 2;
        float2 S0 = *(const float2*)(Sp);
        float2 S1 = *(const float2*)(Sp + 32);
        float2 S2 = *(const float2*)(Sp + 64);
        float lo, hi;
        float2 o;
        UNPACK2(lo, hi, acc2[i][0]);
        o.x = d0 * lo; o.y = d0 * hi;
        UNPACK2(lo, hi, acc2[i][1]);
        o.x += d1 * lo; o.y += d1 * hi;
        UNPACK2(lo, hi, acc2[i][2]);
        o.x += d2 * lo; o.y += d2 * hi;
        o.x += S0.x + S1.x + S2.x;
        o.y += S0.y + S1.y + S2.y;
        if (mask[rown] == 0) { o.x = 0.f; o.y = 0.f; }
        *(float2*)(out + rown * 32 + cq * 2) = o;
    }
}

// ---------------------------------------------------------------------------
extern "C" void kernel_launch(void* const* d_in, const int* in_sizes, int n_in,
                              void* d_out, int out_size)
{
    const float* x    = (const float*)d_in[0];   // [16,1024,32]
    const float* adj  = (const float*)d_in[1];   // [16,1024,1024,3]
    const int*   mask = (const int*)d_in[2];     // [16,1024] bool -> int32
    const float* W    = (const float*)d_in[3];   // [32,96]
    const float* W0   = (const float*)d_in[4];   // [32,96]
    const float* b0   = (const float*)d_in[5];   // [96]
    float*       out  = (float*)d_out;           // [16,1024,32]

    (void)in_sizes; (void)n_in; (void)out_size;

    deg_kernel<<<Bn * Nn, 128>>>(adj, x, W, W0, b0);
    agg_kernel<<<dim3(Nn / 64, Bn), 256>>>(adj, mask, out);
}

// round 12
// speedup vs baseline: 4.9667x; 2.1914x over previous
#include <cuda_runtime.h>
#include <cstdint>

#define Bn 16
#define Nn 1024

// Scratch (device globals; no allocation allowed)
__device__ __align__(128) float g_S[Bn * Nn * 96];     // x@W0 + b0      [row][ec]
__device__ __align__(128) float g_sagg[Bn * Nn * 96];  // dis[m,e]*(x@W) [row][ec] == B[k'][c] flat
__device__ __align__(128) float g_dis[Bn * Nn * 3];    // deg^-1/2       [row][e]

#define FFMA2(d, a, b) \
    asm volatile("fma.rn.f32x2 %0, %1, %2, %0;" : "+l"(d) : "l"(a), "l"(b))
#define DUP2(d, a) \
    asm volatile("mov.b64 %0, {%1,%1};" : "=l"(d) : "f"(a))
#define UNPACK2(lo, hi, v) \
    asm volatile("mov.b64 {%0,%1}, %2;" : "=f"(lo), "=f"(hi) : "l"(v))
#define CPASYNC16(dst, src) \
    asm volatile("cp.async.cg.shared.global [%0], [%1], 16;" :: "r"(dst), "l"(src))
#define CP_COMMIT() asm volatile("cp.async.commit_group;" ::: "memory")
#define CP_WAIT0()  asm volatile("cp.async.wait_group 0;" ::: "memory")

__device__ __forceinline__ uint32_t sptr(const void* p) {
    return (uint32_t)__cvta_generic_to_shared(p);
}

// ---------------------------------------------------------------------------
// Kernel 1 (fused): degrees + per-row linears.  One block (128 thr) per row.
// Consecutive-48B-per-thread e-phase trick keeps the sum divergence-free.
// ---------------------------------------------------------------------------
__global__ __launch_bounds__(128) void deg_kernel(
    const float* __restrict__ adj, const float* __restrict__ x,
    const float* __restrict__ W, const float* __restrict__ W0,
    const float* __restrict__ b0)
{
    int row = blockIdx.x;                    // b*N + n
    const float4* base = (const float4*)(adj + (size_t)row * 3072);
    int t = threadIdx.x;

    __shared__ float xsh[32];
    if (t < 32) xsh[t] = x[(size_t)row * 32 + t];

    float s0 = 0.f, s1 = 0.f, s2 = 0.f;
#pragma unroll
    for (int it = 0; it < 2; it++) {
        int q0 = 3 * (t + it * 128);         // q0 % 3 == 0 always
        float4 v0 = base[q0];
        float4 v1 = base[q0 + 1];
        float4 v2 = base[q0 + 2];
        s0 += v0.x + v0.w + v1.z + v2.y;
        s1 += v0.y + v1.x + v1.w + v2.z;
        s2 += v0.z + v1.y + v2.x + v2.w;
    }
#pragma unroll
    for (int off = 16; off; off >>= 1) {
        s0 += __shfl_down_sync(0xffffffffu, s0, off);
        s1 += __shfl_down_sync(0xffffffffu, s1, off);
        s2 += __shfl_down_sync(0xffffffffu, s2, off);
    }
    __shared__ float red[4][3];
    __shared__ float dis_s[3];
    int w = t >> 5, lane = t & 31;
    if (lane == 0) { red[w][0] = s0; red[w][1] = s1; red[w][2] = s2; }
    __syncthreads();
    if (t < 3) {
        float tot = red[0][t] + red[1][t] + red[2][t] + red[3][t];
        float d = rsqrtf(fmaxf(tot, 1.0f));
        dis_s[t] = d;
        g_dis[(size_t)row * 3 + t] = d;
    }
    __syncthreads();

    if (t < 96) {
        float a = 0.f, a0 = 0.f;
#pragma unroll
        for (int k = 0; k < 32; k++) {
            float xv = xsh[k];
            a  += xv * __ldg(W  + k * 96 + t);
            a0 += xv * __ldg(W0 + k * 96 + t);
        }
        g_sagg[(size_t)row * 96 + t] = dis_s[t >> 5] * a;
        g_S[(size_t)row * 96 + t]    = a0 + __ldg(b0 + t);
    }
}

// ---------------------------------------------------------------------------
// Kernel 2: aggregation as ONE SGEMM with dis folded into A.
//   out[n][c] = mask * ( sum_k' (dis[n,e(k')]*adj[n][k']) * sagg_flat[k'*32+c]
//                        + sum_e S[n][e*32+c] )
// Block = 256 thr (8 warps) = 64 n-rows; warps = (wk k-quarter) x (wn n-half).
// Warp tile 32n x 32c, thread tile 4n x 8c (acc = 16 f32x2).
// K in chunks of 128 k': A transposed + dis-scaled into smem As[k'][64+4pad]
// (LDG.128 -> regs -> 4 STS.32, N=2 banks); B = contiguous 16KB cp.async copy
// (Bs double-buffered).  Compute: per k' 1 A-LDS.128 (conflict-free) +
// 2 B-LDS.128 (bank-broadcast) + 4 DUP2 + 16 FFMA2.
// k-quarter partials merged through smem; epilogue adds S, applies mask.
// ---------------------------------------------------------------------------
#define AS_STRIDE 68                     // floats per k' row: 64 + 4 pad (272B, 16B-aligned)
#define AS_FLOATS (128 * AS_STRIDE)      // 8704 floats = 34816 B
#define BS_FLOATS 4096                   // 128 k' * 32 c
#define SMEM_TOT  ((AS_FLOATS + 2 * BS_FLOATS) * 4)   // 67584 B

__global__ __launch_bounds__(256, 2) void agg_kernel(
    const float* __restrict__ adj,
    const int* __restrict__ mask,
    float* __restrict__ out)
{
    extern __shared__ __align__(16) float sm[];
    float* As = sm;                      // [128 k'][68]
    float* Bs = sm + AS_FLOATS;          // [2][128*32]

    int t = threadIdx.x, w = t >> 5, lane = t & 31;
    int wk = w >> 1, wn = w & 1;         // k-quarter, n-half
    int rg = lane >> 2, cg = lane & 3;   // n-subgroup, c-subgroup
    int b = blockIdx.y, n0 = blockIdx.x * 64;

    // staging role: thread -> (row r, seg phase sb)
    int r = t >> 2, sb = t & 3;
    const float* arow = adj + ((size_t)b * Nn + n0 + r) * 3072;
    const float* sgb  = g_sagg + (size_t)b * Nn * 96;
    uint32_t bs_addr  = sptr(Bs);

    // dis triple for this thread's staged row, pre-rotated by sb%3
    size_t rowr = (size_t)b * Nn + n0 + r;
    float dv0 = g_dis[rowr * 3], dv1 = g_dis[rowr * 3 + 1], dv2 = g_dis[rowr * 3 + 2];
    float da, db, dc;
    {
        int m3 = sb % 3;                 // e of k' = 4*sb (ck=0)
        if (m3 == 0)      { da = dv0; db = dv1; dc = dv2; }
        else if (m3 == 1) { da = dv1; db = dv2; dc = dv0; }
        else              { da = dv2; db = dv0; dc = dv1; }
    }

    unsigned long long acc[4][4];        // [rn][cpair]
#pragma unroll
    for (int i = 0; i < 4; i++)
#pragma unroll
        for (int j = 0; j < 4; j++) acc[i][j] = 0ull;

    float4 av[8];
    auto ldgA = [&](int ck) {
        const float4* p = (const float4*)(arow + ck * 128);
#pragma unroll
        for (int i = 0; i < 8; i++) av[i] = __ldg(p + sb + 4 * i);
    };
    auto cpB = [&](int buf, int ck) {
        const float* src = sgb + (size_t)ck * 4096;
        uint32_t dst = bs_addr + (uint32_t)buf * (BS_FLOATS * 4);
#pragma unroll
        for (int i = 0; i < 4; i++) {
            int q = t + 256 * i;
            CPASYNC16(dst + (uint32_t)q * 16u, src + q * 4);
        }
        CP_COMMIT();
    };
    // STS chunk with dis folding; rotates (da,db,dc) by +2 for next chunk
    // (e(k') advances by 128%3 == 2 per chunk).
    auto stsA = [&]() {
#pragma unroll
        for (int i = 0; i < 8; i++) {
            float m0, m1, m2;
            const int rot = i % 3;       // compile-time per unrolled i
            if (rot == 0)      { m0 = da; m1 = db; m2 = dc; }
            else if (rot == 1) { m0 = db; m1 = dc; m2 = da; }
            else               { m0 = dc; m1 = da; m2 = db; }
            float4 v = av[i];
            int k4 = (sb + 4 * i) * 4;   // k' of component x
            As[(k4 + 0) * AS_STRIDE + r] = v.x * m0;
            As[(k4 + 1) * AS_STRIDE + r] = v.y * m1;
            As[(k4 + 2) * AS_STRIDE + r] = v.z * m2;
            As[(k4 + 3) * AS_STRIDE + r] = v.w * m0;
        }
        float tmp = da; da = dc; dc = db; db = tmp;   // base += 2 (mod 3)
    };

    // prologue
    cpB(0, 0);
    ldgA(0);
    CP_WAIT0();
    stsA();
    __syncthreads();

    for (int ck = 0; ck < 24; ck++) {
        if (ck < 23) { ldgA(ck + 1); cpB((ck + 1) & 1, ck + 1); }

        const float* bptr = Bs + (ck & 1) * BS_FLOATS;
#pragma unroll 2
        for (int kk = 0; kk < 32; kk++) {
            int kp = wk * 32 + kk;
            float4 af = *(const float4*)(As + kp * AS_STRIDE + wn * 32 + rg * 4);
            unsigned long long a0, a1, a2, a3;
            DUP2(a0, af.x); DUP2(a1, af.y); DUP2(a2, af.z); DUP2(a3, af.w);
            ulonglong2 bv0 = *(const ulonglong2*)(bptr + kp * 32 + cg * 8);
            ulonglong2 bv1 = *(const ulonglong2*)(bptr + kp * 32 + cg * 8 + 4);
            FFMA2(acc[0][0], a0, bv0.x); FFMA2(acc[0][1], a0, bv0.y);
            FFMA2(acc[0][2], a0, bv1.x); FFMA2(acc[0][3], a0, bv1.y);
            FFMA2(acc[1][0], a1, bv0.x); FFMA2(acc[1][1], a1, bv0.y);
            FFMA2(acc[1][2], a1, bv1.x); FFMA2(acc[1][3], a1, bv1.y);
            FFMA2(acc[2][0], a2, bv0.x); FFMA2(acc[2][1], a2, bv0.y);
            FFMA2(acc[2][2], a2, bv1.x); FFMA2(acc[2][3], a2, bv1.y);
            FFMA2(acc[3][0], a3, bv0.x); FFMA2(acc[3][1], a3, bv0.y);
            FFMA2(acc[3][2], a3, bv1.x); FFMA2(acc[3][3], a3, bv1.y);
        }
        __syncthreads();                 // all warps done reading As/Bs[ck&1]
        if (ck < 23) {
            stsA();
            CP_WAIT0();
            __syncthreads();             // new As + Bs visible
        }
    }

    // ---- merge k-quarters through smem (As/Bs regions are free now) ----
    // slot per (warp, lane): 36 floats (144B) to de-stride bank conflicts
    float* myslot = sm + (w * 32 + lane) * 36;
#pragma unroll
    for (int p = 0; p < 16; p++) {
        float lo, hi;
        UNPACK2(lo, hi, acc[p >> 2][p & 3]);
        myslot[2 * p]     = lo;
        myslot[2 * p + 1] = hi;
    }
    __syncthreads();

#pragma unroll
    for (int i = 0; i < 4; i++) {
        int o = t + 256 * i;             // 0..1023 = 64n x 16 cpair
        int n = o >> 4, cp = o & 15;
        int wn2 = n >> 5, rg2 = (n >> 2) & 7, rn2 = n & 3;
        int cg2 = cp >> 2, ci2 = cp & 3;
        int baseslot = wn2 * 32 + rg2 * 4 + cg2;
        int foff = (rn2 * 4 + ci2) * 2;
        float lo = 0.f, hi = 0.f;
#pragma unroll
        for (int q = 0; q < 4; q++) {    // k-quarter partials (wk stride = 64 slots)
            const float* ps = sm + (size_t)(q * 64 + baseslot) * 36 + foff;
            lo += ps[0]; hi += ps[1];
        }
        size_t rown = (size_t)b * Nn + n0 + n;
        const float* Sp = g_S + rown * 96 + cp * 2;
        lo += Sp[0] + Sp[32] + Sp[64];
        hi += Sp[1] + Sp[33] + Sp[65];
        if (mask[rown] == 0) { lo = 0.f; hi = 0.f; }
        float2 o2; o2.x = lo; o2.y = hi;
        *(float2*)(out + rown * 32 + cp * 2) = o2;
    }
}

// ---------------------------------------------------------------------------
extern "C" void kernel_launch(void* const* d_in, const int* in_sizes, int n_in,
                              void* d_out, int out_size)
{
    const float* x    = (const float*)d_in[0];   // [16,1024,32]
    const float* adj  = (const float*)d_in[1];   // [16,1024,1024,3]
    const int*   mask = (const int*)d_in[2];     // [16,1024] bool -> int32
    const float* W    = (const float*)d_in[3];   // [32,96]
    const float* W0   = (const float*)d_in[4];   // [32,96]
    const float* b0   = (const float*)d_in[5];   // [96]
    float*       out  = (float*)d_out;           // [16,1024,32]

    (void)in_sizes; (void)n_in; (void)out_size;

    cudaFuncSetAttribute(agg_kernel, cudaFuncAttributeMaxDynamicSharedMemorySize, SMEM_TOT);

    deg_kernel<<<Bn * Nn, 128>>>(adj, x, W, W0, b0);
    agg_kernel<<<dim3(Nn / 64, Bn), 256, SMEM_TOT>>>(adj, mask, out);
}